// round 1
// baseline (speedup 1.0000x reference)
#include <cuda_runtime.h>
#include <math.h>

#define B_  8
#define C_  12
#define S_  784
#define NTOK 785
#define D_  768
#define HH  28
#define PATCH 84
#define GCNH 512

// ---------------- scratch (no allocation allowed) ----------------
__device__ float         g_amap[B_*C_*S_];
__device__ unsigned char g_selflag[B_*C_*S_];
__device__ float         g_struct[B_*D_];
__device__ int           g_pidx[B_*S_];

// ---------------- Kernel A: per (b,c) top-84 select + new_score ----------------
__global__ void kA(const float* __restrict__ x) {
    int bc = blockIdx.x;                      // 0..95  (b*C + c)
    __shared__ float sc[S_];
    const float* base = x + (size_t)bc * NTOK * NTOK + 1;   // x[b,c,0,1:]
    for (int s = threadIdx.x; s < S_; s += blockDim.x) sc[s] = base[s];
    __syncthreads();
    for (int s = threadIdx.x; s < S_; s += blockDim.x) {
        float v = sc[s];
        int rank = 0;
        #pragma unroll 8
        for (int t = 0; t < S_; t++) {
            float u = sc[t];
            rank += (u > v) || (u == v && t < s);   // top_k tie: earlier index wins
        }
        bool sel = rank < PATCH;
        g_amap[bc*S_ + s]    = sel ? v : 0.7f * v;
        g_selflag[bc*S_ + s] = sel ? 1 : 0;
    }
}

// ---------------- Kernel B: per-batch analytics (rank-1 GCN collapse) ----------------
__global__ void kB(const float* __restrict__ w1, const float* __restrict__ w2, int sn) {
    int b = blockIdx.x;
    int t = threadIdx.x;
    const int NT = 256;
    __shared__ float pw[S_];
    __shared__ float binm[S_];    // holds m, then binary, then conv result
    __shared__ float cnt[S_];
    __shared__ float wk[GCNH];
    __shared__ float red[256];
    __shared__ int   redi[256];
    __shared__ float s_mean, s_q0, s_q1, s_ap, s_am, s_panchor;
    __shared__ int   s_anchor;

    // --- m[s] = sum_c amap, pw = m/12, total for mean ---
    float part = 0.f;
    for (int s = t; s < S_; s += NT) {
        float sm = 0.f;
        #pragma unroll
        for (int c = 0; c < C_; c++) sm += g_amap[(b*C_ + c)*S_ + s];
        binm[s] = sm;
        pw[s]   = sm * (1.f/12.f);
        part += sm;
    }
    red[t] = part; __syncthreads();
    for (int o = 128; o > 0; o >>= 1) { if (t < o) red[t] += red[t+o]; __syncthreads(); }
    if (t == 0) s_mean = red[0] / (float)S_;
    __syncthreads();
    float mean = s_mean;
    for (int s = t; s < S_; s += NT) binm[s] = (binm[s] > mean) ? 1.f : 0.f;
    __syncthreads();

    // --- anchor = argmax_s binary[s]*pw[s], first-index tie break ---
    float bv = -1e30f; int bi = S_;
    for (int s = t; s < S_; s += NT) {
        float v = binm[s] * pw[s];
        if (v > bv || (v == bv && s < bi)) { bv = v; bi = s; }
    }
    red[t] = bv; redi[t] = bi; __syncthreads();
    for (int o = 128; o > 0; o >>= 1) {
        if (t < o) {
            float v2 = red[t+o]; int i2 = redi[t+o];
            if (v2 > red[t] || (v2 == red[t] && i2 < redi[t])) { red[t] = v2; redi[t] = i2; }
        }
        __syncthreads();
    }
    if (t == 0) { s_anchor = redi[0]; s_panchor = pw[redi[0]]; }
    __syncthreads();
    int anchor = s_anchor;
    float ai = (float)(anchor / HH), aj = (float)(anchor % HH);

    // --- q0,q1 = pw^T [dist, ang];  A+ / A- = sum pw^2 split by sign ---
    float q0 = 0.f, q1 = 0.f, apos = 0.f, aneg = 0.f;
    for (int s = t; s < S_; s += NT) {
        float rx = ((float)(s / HH) - ai) / 28.0f;
        float ry = ((float)(s % HH) - aj) / 28.0f;
        float dist = sqrtf(rx*rx + ry*ry);
        float ang  = (atan2f(ry, rx) / (float)M_PI + 1.f) * 0.5f;
        float p = pw[s];
        q0 += p * dist;
        q1 += p * ang;
        if (p > 0.f) apos += p*p; else if (p < 0.f) aneg += p*p;
    }
    // four reductions
    red[t] = q0;   __syncthreads();
    for (int o = 128; o > 0; o >>= 1) { if (t < o) red[t] += red[t+o]; __syncthreads(); }
    if (t == 0) s_q0 = red[0]; __syncthreads();
    red[t] = q1;   __syncthreads();
    for (int o = 128; o > 0; o >>= 1) { if (t < o) red[t] += red[t+o]; __syncthreads(); }
    if (t == 0) s_q1 = red[0]; __syncthreads();
    red[t] = apos; __syncthreads();
    for (int o = 128; o > 0; o >>= 1) { if (t < o) red[t] += red[t+o]; __syncthreads(); }
    if (t == 0) s_ap = red[0]; __syncthreads();
    red[t] = aneg; __syncthreads();
    for (int o = 128; o > 0; o >>= 1) { if (t < o) red[t] += red[t+o]; __syncthreads(); }
    if (t == 0) s_am = red[0]; __syncthreads();

    float Q0 = s_q0, Q1 = s_q1, AP = s_ap, AM = s_am;

    // --- w[k] = v1[k] * (v1>0 ? A+ : A-),  v1 = q @ W1 ---
    for (int k = t; k < GCNH; k += NT) {
        float v = Q0 * w1[k] + Q1 * w1[GCNH + k];
        wk[k] = (v > 0.f) ? v * AP : ((v < 0.f) ? v * AM : 0.f);
    }
    __syncthreads();

    // --- struct row at anchor: leaky( pw[anchor] * (w @ W2) ) ---
    float pa = s_panchor;
    for (int kp = t; kp < D_; kp += NT) {
        float acc = 0.f;
        #pragma unroll 8
        for (int j = 0; j < GCNH; j++) acc += wk[j] * w2[j*D_ + kp];
        float o2 = pa * acc;
        g_struct[b*D_ + kp] = (o2 > 0.f) ? o2 : 0.2f * o2;
    }

    // --- count[s] = #channels selected; 3x3 [1 2 1;2 4 2;1 2 1] conv, zero pad ---
    for (int s = t; s < S_; s += NT) {
        int c = 0;
        #pragma unroll
        for (int ch = 0; ch < C_; ch++) c += g_selflag[(b*C_ + ch)*S_ + s];
        cnt[s] = (float)c;
    }
    __syncthreads();
    for (int s = t; s < S_; s += NT) {
        int li = s / HH, lj = s % HH;
        float acc = 0.f;
        #pragma unroll
        for (int di = -1; di <= 1; di++) {
            #pragma unroll
            for (int dj = -1; dj <= 1; dj++) {
                int ni = li + di, nj = lj + dj;
                if (ni >= 0 && ni < HH && nj >= 0 && nj < HH) {
                    float kw = ((di == 0) ? 2.f : 1.f) * ((dj == 0) ? 2.f : 1.f);
                    acc += kw * cnt[ni*HH + nj];
                }
            }
        }
        binm[s] = acc;   // reuse
    }
    __syncthreads();

    // --- stable descending argsort: rank = #(cnt2>v) + #(==v, earlier idx) ---
    for (int s = t; s < S_; s += NT) {
        float v = binm[s];
        int r = 0;
        #pragma unroll 8
        for (int u = 0; u < S_; u++) {
            float vu = binm[u];
            r += (vu > v) || (vu == v && u < s);
        }
        if (r < sn) g_pidx[b*S_ + r] = s + 1;
    }
}

// ---------------- Kernel C: streaming copy + row0 add + gather ----------------
__global__ void kC(const float* __restrict__ hs, float* __restrict__ out,
                   int sn, size_t nhs4, size_t nsel4) {
    size_t i = (size_t)blockIdx.x * blockDim.x + threadIdx.x;
    const float4* in4 = (const float4*)hs;
    float4* out4 = (float4*)out;
    if (i < nhs4) {
        float4 v = in4[i];
        size_t k4 = i % (D_/4);
        size_t r  = (i / (D_/4)) % NTOK;
        if (r == 0) {
            size_t b = i / ((size_t)(D_/4) * NTOK);
            const float* st = &g_struct[b*D_ + k4*4];
            v.x += st[0]; v.y += st[1]; v.z += st[2]; v.w += st[3];
        }
        out4[i] = v;
    } else if (i < nhs4 + nsel4) {
        size_t j  = i - nhs4;
        size_t k4 = j % (D_/4);
        size_t jj = (j / (D_/4)) % (size_t)sn;
        size_t b  = j / ((size_t)(D_/4) * sn);
        int row = g_pidx[b*S_ + jj];
        out4[nhs4 + j] = in4[((size_t)b*NTOK + row)*(D_/4) + k4];
    }
}

// ---------------- launch ----------------
extern "C" void kernel_launch(void* const* d_in, const int* in_sizes, int n_in,
                              void* d_out, int out_size) {
    const float* hs = (const float*)d_in[0];
    const float* x  = (const float*)d_in[1];
    const float* w1 = (const float*)d_in[2];
    const float* w2 = (const float*)d_in[3];
    (void)in_sizes; (void)n_in;

    int sn = out_size / (B_ * D_) - NTOK;     // selected rows per batch
    if (sn < 0) sn = 0;
    if (sn > S_) sn = S_;

    kA<<<B_*C_, 256>>>(x);
    kB<<<B_, 256>>>(w1, w2, sn);

    size_t nhs4  = (size_t)B_ * NTOK * (D_/4);
    size_t nsel4 = (size_t)B_ * sn * (D_/4);
    size_t tot   = nhs4 + nsel4;
    kC<<<(unsigned)((tot + 255) / 256), 256>>>(hs, (float*)d_out, sn, nhs4, nsel4);
}

// round 2
// speedup vs baseline: 1.9240x; 1.9240x over previous
#include <cuda_runtime.h>
#include <math.h>

#define B_  8
#define C_  12
#define S_  784
#define NTOK 785
#define D_  768
#define HH  28
#define PATCH 84
#define GCNH 512

// ---------------- scratch (no allocation allowed) ----------------
__device__ float         g_amap[B_*C_*S_];
__device__ unsigned char g_selflag[B_*C_*S_];
__device__ float         g_struct[B_*D_];
__device__ int           g_pidx[B_*S_];
__device__ int           g_key[B_*S_];

// monotone float->uint mapping: a > b  <=>  f2u(a) > f2u(b)
__device__ __forceinline__ unsigned f2u(float f) {
    unsigned u = __float_as_uint(f);
    return (u & 0x80000000u) ? ~u : (u | 0x80000000u);
}

// ---------------- Kernel A: per (b,c) top-84 via radix select ----------------
__global__ void kA(const float* __restrict__ x) {
    int bc = blockIdx.x;                      // 0..95  (b*C + c)
    int t  = threadIdx.x;                     // 256 threads
    __shared__ float    sc[S_];
    __shared__ unsigned key[S_];
    __shared__ int      hist[256];
    __shared__ unsigned s_prefix;
    __shared__ int      s_k;

    const float* base = x + (size_t)bc * NTOK * NTOK + 1;   // x[b,c,0,1:]
    for (int s = t; s < S_; s += 256) {
        float v = base[s];
        sc[s]  = v;
        key[s] = f2u(v);
    }
    if (t == 0) { s_prefix = 0u; s_k = PATCH; }
    __syncthreads();

    // 4 radix passes, high byte first: find the 84th-largest key exactly
    for (int p = 0; p < 4; p++) {
        int shift = 24 - 8 * p;
        hist[t] = 0;
        __syncthreads();
        unsigned pref = s_prefix;
        for (int s = t; s < S_; s += 256) {
            unsigned kk = key[s];
            bool cand;
            if (p == 0) cand = true;
            else        cand = (((kk ^ pref) >> (shift + 8)) == 0u);
            if (cand) atomicAdd(&hist[(kk >> shift) & 255], 1);
        }
        __syncthreads();
        // suffix sums (cum-from-top): hist[b] := sum_{b'>=b} hist[b']
        for (int off = 1; off < 256; off <<= 1) {
            int add = (t + off < 256) ? hist[t + off] : 0;
            __syncthreads();
            hist[t] += add;
            __syncthreads();
        }
        int k = s_k;
        __syncthreads();              // everyone has read s_k before writer updates
        int above = (t < 255) ? hist[t + 1] : 0;
        if (hist[t] >= k && above < k) {      // unique bin
            s_prefix = pref | ((unsigned)t << shift);
            s_k      = k - above;
        }
        __syncthreads();
    }

    unsigned T  = s_prefix;   // exact 84th-largest key value
    int     neq = s_k;        // how many elements equal to T get selected (earliest idx)
    for (int s = t; s < S_; s += 256) {
        unsigned kk = key[s];
        bool sel;
        if (kk > T) sel = true;
        else if (kk == T) {
            int eq = 0;
            for (int u = 0; u < s; u++) eq += (key[u] == T);
            sel = eq < neq;
        } else sel = false;
        float v = sc[s];
        g_amap[bc*S_ + s]    = sel ? v : 0.7f * v;
        g_selflag[bc*S_ + s] = sel ? 1 : 0;
    }
}

// ---------------- Kernel B: per-batch analytics (rank-1 GCN collapse) ----------------
__global__ void kB(const float* __restrict__ w1, const float* __restrict__ w2) {
    int b = blockIdx.x;
    int t = threadIdx.x;
    const int NT = 256;
    __shared__ float  pw[S_];
    __shared__ float  binm[S_];
    __shared__ float  cnt[S_];
    __shared__ float  wk[GCNH];
    __shared__ float4 red4[256];
    __shared__ float  red[256];
    __shared__ int    redi[256];
    __shared__ float  s_mean, s_panchor;
    __shared__ float4 s_q;
    __shared__ int    s_anchor;

    // --- m[s] = sum_c amap; pw = m/12; mean ---
    float part = 0.f;
    for (int s = t; s < S_; s += NT) {
        float sm = 0.f;
        #pragma unroll
        for (int c = 0; c < C_; c++) sm += g_amap[(b*C_ + c)*S_ + s];
        binm[s] = sm;
        pw[s]   = sm * (1.f/12.f);
        part += sm;
    }
    red[t] = part; __syncthreads();
    for (int o = 128; o > 0; o >>= 1) { if (t < o) red[t] += red[t+o]; __syncthreads(); }
    if (t == 0) s_mean = red[0] / (float)S_;
    __syncthreads();
    float mean = s_mean;
    for (int s = t; s < S_; s += NT) binm[s] = (binm[s] > mean) ? 1.f : 0.f;
    __syncthreads();

    // --- anchor = argmax_s binary[s]*pw[s] (first index wins) ---
    float bv = -1e30f; int bi = S_;
    for (int s = t; s < S_; s += NT) {
        float v = binm[s] * pw[s];
        if (v > bv || (v == bv && s < bi)) { bv = v; bi = s; }
    }
    red[t] = bv; redi[t] = bi; __syncthreads();
    for (int o = 128; o > 0; o >>= 1) {
        if (t < o) {
            float v2 = red[t+o]; int i2 = redi[t+o];
            if (v2 > red[t] || (v2 == red[t] && i2 < redi[t])) { red[t] = v2; redi[t] = i2; }
        }
        __syncthreads();
    }
    if (t == 0) { s_anchor = redi[0]; s_panchor = pw[redi[0]]; }
    __syncthreads();
    int anchor = s_anchor;
    float ai = (float)(anchor / HH), aj = (float)(anchor % HH);

    // --- fused reduction: q0 = pw.dist, q1 = pw.ang, A+ = sum pw^2 (pw>0), A- (pw<0) ---
    float4 acc4 = make_float4(0.f, 0.f, 0.f, 0.f);
    for (int s = t; s < S_; s += NT) {
        float rx = ((float)(s / HH) - ai) / 28.0f;
        float ry = ((float)(s % HH) - aj) / 28.0f;
        float dist = sqrtf(rx*rx + ry*ry);
        float ang  = (atan2f(ry, rx) / (float)M_PI + 1.f) * 0.5f;
        float p = pw[s];
        acc4.x += p * dist;
        acc4.y += p * ang;
        if (p > 0.f) acc4.z += p*p; else if (p < 0.f) acc4.w += p*p;
    }
    red4[t] = acc4; __syncthreads();
    for (int o = 128; o > 0; o >>= 1) {
        if (t < o) {
            float4 a = red4[t], c = red4[t+o];
            a.x += c.x; a.y += c.y; a.z += c.z; a.w += c.w;
            red4[t] = a;
        }
        __syncthreads();
    }
    if (t == 0) s_q = red4[0];
    __syncthreads();
    float Q0 = s_q.x, Q1 = s_q.y, AP = s_q.z, AM = s_q.w;

    // --- w[k] = v1[k] * (v1>0 ? A+ : A-),  v1 = q @ W1 ---
    for (int k = t; k < GCNH; k += NT) {
        float v = Q0 * w1[k] + Q1 * w1[GCNH + k];
        wk[k] = (v > 0.f) ? v * AP : ((v < 0.f) ? v * AM : 0.f);
    }
    __syncthreads();

    // --- struct row at anchor: leaky( pw[anchor] * (w @ W2) ), 3 cols/thread ---
    float pa = s_panchor;
    {
        float a0 = 0.f, a1 = 0.f, a2 = 0.f;
        const float* w2c = w2 + t;
        #pragma unroll 4
        for (int j = 0; j < GCNH; j++) {
            float wj = wk[j];
            const float* r = w2c + j * D_;
            a0 += wj * r[0];
            a1 += wj * r[256];
            a2 += wj * r[512];
        }
        float o0 = pa * a0, o1 = pa * a1, o2 = pa * a2;
        g_struct[b*D_ + t      ] = (o0 > 0.f) ? o0 : 0.2f * o0;
        g_struct[b*D_ + t + 256] = (o1 > 0.f) ? o1 : 0.2f * o1;
        g_struct[b*D_ + t + 512] = (o2 > 0.f) ? o2 : 0.2f * o2;
    }

    // --- count -> 3x3 conv -> composite int key (desc value, stable asc index) ---
    for (int s = t; s < S_; s += NT) {
        int c = 0;
        #pragma unroll
        for (int ch = 0; ch < C_; ch++) c += g_selflag[(b*C_ + ch)*S_ + s];
        cnt[s] = (float)c;
    }
    __syncthreads();
    for (int s = t; s < S_; s += NT) {
        int li = s / HH, lj = s % HH;
        float acc = 0.f;
        #pragma unroll
        for (int di = -1; di <= 1; di++) {
            #pragma unroll
            for (int dj = -1; dj <= 1; dj++) {
                int ni = li + di, nj = lj + dj;
                if (ni >= 0 && ni < HH && nj >= 0 && nj < HH) {
                    float kw = ((di == 0) ? 2.f : 1.f) * ((dj == 0) ? 2.f : 1.f);
                    acc += kw * cnt[ni*HH + nj];
                }
            }
        }
        // conv result is an exact small integer; larger key == earlier in order
        g_key[b*S_ + s] = (int)acc * 1024 + (1023 - s);
    }
}

// ---------------- Kernel kRank: stable descending rank via int keys ----------------
__global__ void kRank(int sn) {
    int b    = blockIdx.x >> 2;        // batch
    int part = blockIdx.x & 3;         // quarter of s-range
    int t    = threadIdx.x;
    __shared__ int kk[S_];
    for (int s = t; s < S_; s += 256) kk[s] = g_key[b*S_ + s];
    __syncthreads();
    int s = part * 196 + t;
    if (t < 196) {
        int ks = kk[s];
        int r = 0;
        #pragma unroll 8
        for (int u = 0; u < S_; u++) r += (kk[u] > ks);
        if (r < sn) g_pidx[b*S_ + r] = s + 1;
    }
}

// ---------------- Kernel C: streaming copy + row0 add + gather ----------------
__global__ void kC(const float* __restrict__ hs, float* __restrict__ out,
                   int sn, size_t nhs4, size_t nsel4) {
    size_t i = (size_t)blockIdx.x * blockDim.x + threadIdx.x;
    const float4* in4 = (const float4*)hs;
    float4* out4 = (float4*)out;
    if (i < nhs4) {
        float4 v = in4[i];
        size_t k4 = i % (D_/4);
        size_t r  = (i / (D_/4)) % NTOK;
        if (r == 0) {
            size_t b = i / ((size_t)(D_/4) * NTOK);
            const float* st = &g_struct[b*D_ + k4*4];
            v.x += st[0]; v.y += st[1]; v.z += st[2]; v.w += st[3];
        }
        out4[i] = v;
    } else if (i < nhs4 + nsel4) {
        size_t j  = i - nhs4;
        size_t k4 = j % (D_/4);
        size_t jj = (j / (D_/4)) % (size_t)sn;
        size_t b  = j / ((size_t)(D_/4) * sn);
        int row = g_pidx[b*S_ + jj];
        out4[nhs4 + j] = in4[((size_t)b*NTOK + row)*(D_/4) + k4];
    }
}

// ---------------- launch ----------------
extern "C" void kernel_launch(void* const* d_in, const int* in_sizes, int n_in,
                              void* d_out, int out_size) {
    const float* hs = (const float*)d_in[0];
    const float* x  = (const float*)d_in[1];
    const float* w1 = (const float*)d_in[2];
    const float* w2 = (const float*)d_in[3];
    (void)in_sizes; (void)n_in;

    int sn = out_size / (B_ * D_) - NTOK;     // selected rows per batch
    if (sn < 0) sn = 0;
    if (sn > S_) sn = S_;

    kA<<<B_*C_, 256>>>(x);
    kB<<<B_, 256>>>(w1, w2);
    kRank<<<B_*4, 256>>>(sn);

    size_t nhs4  = (size_t)B_ * NTOK * (D_/4);
    size_t nsel4 = (size_t)B_ * sn * (D_/4);
    size_t tot   = nhs4 + nsel4;
    kC<<<(unsigned)((tot + 255) / 256), 256>>>(hs, (float*)d_out, sn, nhs4, nsel4);
}

// round 6
// speedup vs baseline: 3.2969x; 1.7135x over previous
#include <cuda_runtime.h>
#include <math.h>

#define B_  8
#define C_  12
#define S_  784
#define NTOK 785
#define D_  768
#define HH  28
#define PATCH 84
#define GCNH 512

// ---------------- scratch (no allocation allowed) ----------------
__device__ float         g_amap[B_*C_*S_];
__device__ unsigned char g_selflag[B_*C_*S_];
__device__ float         g_struct[B_*D_];
__device__ float         g_wk[B_*GCNH];
__device__ int           g_pidx[B_*S_];
__device__ int           g_key[B_*S_];

// monotone float->uint mapping: a > b  <=>  f2u(a) > f2u(b)
__device__ __forceinline__ unsigned f2u(float f) {
    unsigned u = __float_as_uint(f);
    return (u & 0x80000000u) ? ~u : (u | 0x80000000u);
}

// ---------------- Kernel A: per (b,c) top-84 via radix select (shuffle scan) ----
__global__ void kA(const float* __restrict__ x) {
    int bc = blockIdx.x;                      // 0..95  (b*C + c)
    int t  = threadIdx.x;                     // 256 threads
    unsigned lane = t & 31;
    int wid = t >> 5;
    __shared__ float    sc[S_];
    __shared__ unsigned key[S_];
    __shared__ int      hist[256];
    __shared__ int      wtot[8];
    __shared__ unsigned s_prefix;
    __shared__ int      s_k;

    const float* base = x + (size_t)bc * NTOK * NTOK + 1;   // x[b,c,0,1:]
    for (int s = t; s < S_; s += 256) {
        float v = base[s];
        sc[s]  = v;
        key[s] = f2u(v);
    }
    if (t == 0) { s_prefix = 0u; s_k = PATCH; }

    #pragma unroll
    for (int p = 0; p < 4; p++) {
        int shift = 24 - 8 * p;
        hist[t] = 0;
        __syncthreads();                       // publishes s_prefix/s_k too
        unsigned pref = s_prefix;
        int      k    = s_k;
        for (int s = t; s < S_; s += 256) {
            unsigned kk = key[s];
            bool cand = (p == 0) || (((kk ^ pref) >> (shift + 8)) == 0u);
            if (cand) atomicAdd(&hist[(kk >> shift) & 255], 1);
        }
        __syncthreads();
        int v = hist[t];
        int xsum = v;
        #pragma unroll
        for (int off = 1; off < 32; off <<= 1) {
            int y = __shfl_down_sync(0xFFFFFFFFu, xsum, off);
            if (lane + off < 32) xsum += y;
        }
        if (lane == 0) wtot[wid] = xsum;       // warp total
        __syncthreads();
        int addhi = 0;
        for (int ww = wid + 1; ww < 8; ww++) addhi += wtot[ww];
        int suffix = xsum + addhi;             // # keys with bin >= t (among candidates)
        int above  = suffix - v;               // # keys with bin >  t
        if (suffix >= k && above < k) {        // exactly one thread matches
            s_prefix = pref | ((unsigned)t << shift);
            s_k      = k - above;
        }
    }
    __syncthreads();

    unsigned T  = s_prefix;   // exact 84th-largest key value
    int     neq = s_k;        // #elements equal to T that get selected (earliest idx)
    for (int s = t; s < S_; s += 256) {
        unsigned kk = key[s];
        bool sel;
        if (kk > T) sel = true;
        else if (kk == T) {
            int eq = 0;
            for (int u = 0; u < s; u++) eq += (key[u] == T);
            sel = eq < neq;
        } else sel = false;
        float v = sc[s];
        g_amap[bc*S_ + s]    = sel ? v : 0.7f * v;
        g_selflag[bc*S_ + s] = sel ? 1 : 0;
    }
}

// ---------------- Kernel B: per-batch analytics (no matvec here) ----------------
__global__ void kB(const float* __restrict__ w1) {
    int b = blockIdx.x;
    int t = threadIdx.x;
    const int NT = 256;
    __shared__ float  pw[S_];
    __shared__ float  binm[S_];
    __shared__ float  cnt[S_];
    __shared__ float4 red4[256];
    __shared__ float  red[256];
    __shared__ int    redi[256];
    __shared__ float  s_mean, s_panchor;
    __shared__ float4 s_q;
    __shared__ int    s_anchor;

    // --- m[s] = sum_c amap; pw = m/12; mean ---
    float part = 0.f;
    for (int s = t; s < S_; s += NT) {
        float sm = 0.f;
        #pragma unroll
        for (int c = 0; c < C_; c++) sm += g_amap[(b*C_ + c)*S_ + s];
        binm[s] = sm;
        pw[s]   = sm * (1.f/12.f);
        part += sm;
    }
    red[t] = part; __syncthreads();
    for (int o = 128; o > 0; o >>= 1) { if (t < o) red[t] += red[t+o]; __syncthreads(); }
    if (t == 0) s_mean = red[0] / (float)S_;
    __syncthreads();
    float mean = s_mean;
    for (int s = t; s < S_; s += NT) binm[s] = (binm[s] > mean) ? 1.f : 0.f;
    __syncthreads();

    // --- anchor = argmax_s binary[s]*pw[s] (first index wins) ---
    float bv = -1e30f; int bi = S_;
    for (int s = t; s < S_; s += NT) {
        float v = binm[s] * pw[s];
        if (v > bv || (v == bv && s < bi)) { bv = v; bi = s; }
    }
    red[t] = bv; redi[t] = bi; __syncthreads();
    for (int o = 128; o > 0; o >>= 1) {
        if (t < o) {
            float v2 = red[t+o]; int i2 = redi[t+o];
            if (v2 > red[t] || (v2 == red[t] && i2 < redi[t])) { red[t] = v2; redi[t] = i2; }
        }
        __syncthreads();
    }
    if (t == 0) { s_anchor = redi[0]; s_panchor = pw[redi[0]]; }
    __syncthreads();
    int anchor = s_anchor;
    float ai = (float)(anchor / HH), aj = (float)(anchor % HH);

    // --- fused reduction: q0 = pw.dist, q1 = pw.ang, A+/A- = sum pw^2 by sign ---
    float4 acc4 = make_float4(0.f, 0.f, 0.f, 0.f);
    for (int s = t; s < S_; s += NT) {
        float rx = ((float)(s / HH) - ai) / 28.0f;
        float ry = ((float)(s % HH) - aj) / 28.0f;
        float dist = sqrtf(rx*rx + ry*ry);
        float ang  = (atan2f(ry, rx) / (float)M_PI + 1.f) * 0.5f;
        float p = pw[s];
        acc4.x += p * dist;
        acc4.y += p * ang;
        if (p > 0.f) acc4.z += p*p; else if (p < 0.f) acc4.w += p*p;
    }
    red4[t] = acc4; __syncthreads();
    for (int o = 128; o > 0; o >>= 1) {
        if (t < o) {
            float4 a = red4[t], c = red4[t+o];
            a.x += c.x; a.y += c.y; a.z += c.z; a.w += c.w;
            red4[t] = a;
        }
        __syncthreads();
    }
    if (t == 0) s_q = red4[0];
    __syncthreads();
    float Q0 = s_q.x, Q1 = s_q.y, AP = s_q.z, AM = s_q.w;
    float pa = s_panchor;

    // --- g_wk[k] = pa * v1[k] * (v1>0 ? A+ : A-),  v1 = q @ W1 ---
    for (int k = t; k < GCNH; k += NT) {
        float v = Q0 * w1[k] + Q1 * w1[GCNH + k];
        float wv = (v > 0.f) ? v * AP : ((v < 0.f) ? v * AM : 0.f);
        g_wk[b*GCNH + k] = pa * wv;
    }

    // --- count -> 3x3 conv -> composite int key (desc value, stable asc index) ---
    for (int s = t; s < S_; s += NT) {
        int c = 0;
        #pragma unroll
        for (int ch = 0; ch < C_; ch++) c += g_selflag[(b*C_ + ch)*S_ + s];
        cnt[s] = (float)c;
    }
    __syncthreads();
    for (int s = t; s < S_; s += NT) {
        int li = s / HH, lj = s % HH;
        float acc = 0.f;
        #pragma unroll
        for (int di = -1; di <= 1; di++) {
            #pragma unroll
            for (int dj = -1; dj <= 1; dj++) {
                int ni = li + di, nj = lj + dj;
                if (ni >= 0 && ni < HH && nj >= 0 && nj < HH) {
                    float kw = ((di == 0) ? 2.f : 1.f) * ((dj == 0) ? 2.f : 1.f);
                    acc += kw * cnt[ni*HH + nj];
                }
            }
        }
        g_key[b*S_ + s] = (int)acc * 1024 + (1023 - s);   // conv is exact small int
    }
}

// ---------------- kFuse: matvec (blocks 0..191) + rank (blocks 192..223) ------
__global__ void kFuse(const float* __restrict__ w2, int sn) {
    int blk = blockIdx.x;
    int t   = threadIdx.x;
    if (blk < B_ * 24) {
        // matvec: 32 output columns per block, 8-way j-split
        int b    = blk / 24;
        int tile = blk - b * 24;
        __shared__ float wk[GCNH];
        __shared__ float partr[256];
        for (int k = t; k < GCNH; k += 256) wk[k] = g_wk[b*GCNH + k];
        __syncthreads();
        int col = tile * 32 + (t & 31);
        int jq  = t >> 5;                      // 0..7
        const float* w2p = w2 + col;
        float acc = 0.f;
        int j0 = jq * 64;
        #pragma unroll 8
        for (int j = 0; j < 64; j++) acc += wk[j0 + j] * w2p[(size_t)(j0 + j) * D_];
        partr[t] = acc;
        __syncthreads();
        if (t < 32) {
            float o = 0.f;
            #pragma unroll
            for (int q = 0; q < 8; q++) o += partr[t + q*32];
            int c = tile * 32 + t;
            g_struct[b*D_ + c] = (o > 0.f) ? o : 0.2f * o;
        }
    } else {
        // stable descending rank via int keys
        int idx  = blk - B_ * 24;              // 0..31
        int b    = idx >> 2;
        int part = idx & 3;
        __shared__ int kk[S_];
        for (int s = t; s < S_; s += 256) kk[s] = g_key[b*S_ + s];
        __syncthreads();
        if (t < 196) {
            int s = part * 196 + t;
            int ks = kk[s];
            int r = 0;
            #pragma unroll 8
            for (int u = 0; u < S_; u++) r += (kk[u] > ks);
            if (r < sn) g_pidx[b*S_ + r] = s + 1;
        }
    }
}

// ---------------- Kernel C: streaming copy + row0 add + gather (u32, ILP=2) ---
// copy region = B*785*192 = 1,205,760 float4 = exactly 2355 blocks of 512
#define NHS4   1205760u
#define CPBLK  2355u
__global__ void kC(const float4* __restrict__ in4, float4* __restrict__ out4,
                   unsigned sn, unsigned ntot) {
    unsigned t  = threadIdx.x;
    unsigned i0 = blockIdx.x * 512u + t;
    if (blockIdx.x < CPBLK) {
        unsigned i1 = i0 + 256u;
        float4 a = in4[i0];
        float4 b4 = in4[i1];
        unsigned m0 = i0 % 150720u;            // 785*192: row-0 of batch iff < 192
        unsigned m1 = i1 % 150720u;
        if (m0 < 192u) {
            unsigned b = i0 / 150720u;
            float4 st = ((const float4*)g_struct)[b*192u + m0];
            a.x += st.x; a.y += st.y; a.z += st.z; a.w += st.w;
        }
        if (m1 < 192u) {
            unsigned b = i1 / 150720u;
            float4 st = ((const float4*)g_struct)[b*192u + m1];
            b4.x += st.x; b4.y += st.y; b4.z += st.z; b4.w += st.w;
        }
        out4[i0] = a;
        out4[i1] = b4;
    } else {
        #pragma unroll
        for (int e = 0; e < 2; e++) {
            unsigned i = i0 + (unsigned)e * 256u;
            if (i < ntot) {
                unsigned j  = i - NHS4;
                unsigned rr = j / 192u;            // b*sn + jj
                unsigned k4 = j - rr * 192u;
                unsigned b  = rr / sn;
                unsigned jj = rr - b * sn;
                unsigned row = (unsigned)g_pidx[b*S_ + jj];
                out4[i] = in4[(b*785u + row)*192u + k4];
            }
        }
    }
}

// ---------------- launch ----------------
extern "C" void kernel_launch(void* const* d_in, const int* in_sizes, int n_in,
                              void* d_out, int out_size) {
    const float* hs = (const float*)d_in[0];
    const float* x  = (const float*)d_in[1];
    const float* w1 = (const float*)d_in[2];
    const float* w2 = (const float*)d_in[3];
    (void)in_sizes; (void)n_in;

    int sn = out_size / (B_ * D_) - NTOK;     // selected rows per batch
    if (sn < 0) sn = 0;
    if (sn > S_) sn = S_;

    kA<<<B_*C_, 256>>>(x);
    kB<<<B_, 256>>>(w1);
    kFuse<<<B_*24 + B_*4, 256>>>(w2, sn);

    unsigned ntot = NHS4 + (unsigned)(B_ * sn) * 192u;
    unsigned nblk = (ntot + 511u) / 512u;
    kC<<<nblk, 256>>>((const float4*)hs, (float4*)d_out, (unsigned)sn, ntot);
}

// round 8
// speedup vs baseline: 3.4876x; 1.0579x over previous
#include <cuda_runtime.h>
#include <math.h>

#define B_  8
#define C_  12
#define S_  784
#define NTOK 785
#define D_  768
#define HH  28
#define PATCH 84
#define GCNH 512

// sizes in float4 units
#define ROWF4    192u          /* 768 floats per row */
#define BATF4    150720u       /* 785*192 per batch  */
#define NHS4     1205760u      /* 8*785*192          */
#define COPYF4   1204224u      /* 8*784*192 (rows 1..784) */
#define NCHUNK   1176u         /* COPYF4 / 1024      */
#define CH_A     588u
#define CH_B     294u
#define CH_F     294u

// ---------------- scratch (no allocation allowed) ----------------
__device__ float         g_amap[B_*C_*S_];
__device__ unsigned char g_selflag[B_*C_*S_];
__device__ float         g_struct[B_*D_];
__device__ float         g_wk[B_*GCNH];
__device__ int           g_pidx[B_*S_];
__device__ int           g_key[B_*S_];

// monotone float->uint mapping: a > b  <=>  f2u(a) > f2u(b)
__device__ __forceinline__ unsigned f2u(float f) {
    unsigned u = __float_as_uint(f);
    return (u & 0x80000000u) ? ~u : (u | 0x80000000u);
}

// ---- bulk copy of rows 1..784 (src == dst index; ILP=4, batched loads) ------
__device__ __forceinline__ void copyChunk(const float4* __restrict__ in4,
                                          float4* __restrict__ out4, unsigned chunk) {
    unsigned m0 = chunk * 1024u + threadIdx.x;
    unsigned src[4]; float4 v[4];
    #pragma unroll
    for (int e = 0; e < 4; e++) {
        unsigned m = m0 + (unsigned)e * 256u;       // m in [0, COPYF4)
        unsigned b = m / 150528u;                   // 784*192 per batch in copy domain
        src[e] = m + (b + 1u) * ROWF4;              // skip row 0 of each batch
    }
    #pragma unroll
    for (int e = 0; e < 4; e++) v[e] = in4[src[e]];
    #pragma unroll
    for (int e = 0; e < 4; e++) out4[src[e]] = v[e];
}

// ---------------- Kernel A: top-84 radix select (blocks 0..95) + copy --------
__global__ void __launch_bounds__(256) kA(const float* __restrict__ x,
                                          const float4* __restrict__ in4,
                                          float4* __restrict__ out4) {
    if (blockIdx.x >= 96) { copyChunk(in4, out4, blockIdx.x - 96u); return; }
    int bc = blockIdx.x;                      // b*C + c
    int t  = threadIdx.x;
    unsigned lane = t & 31;
    int wid = t >> 5;
    __shared__ float    sc[S_];
    __shared__ unsigned key[S_];
    __shared__ int      hist[256];
    __shared__ int      wtot[8];
    __shared__ unsigned s_prefix;
    __shared__ int      s_k;

    const float* base = x + (size_t)bc * NTOK * NTOK + 1;   // x[b,c,0,1:]
    for (int s = t; s < S_; s += 256) {
        float v = base[s];
        sc[s]  = v;
        key[s] = f2u(v);
    }
    if (t == 0) { s_prefix = 0u; s_k = PATCH; }

    #pragma unroll
    for (int p = 0; p < 4; p++) {
        int shift = 24 - 8 * p;
        hist[t] = 0;
        __syncthreads();                       // publishes s_prefix/s_k too
        unsigned pref = s_prefix;
        int      k    = s_k;
        for (int s = t; s < S_; s += 256) {
            unsigned kk = key[s];
            bool cand = (p == 0) || (((kk ^ pref) >> (shift + 8)) == 0u);
            if (cand) atomicAdd(&hist[(kk >> shift) & 255], 1);
        }
        __syncthreads();
        int v = hist[t];
        int xsum = v;
        #pragma unroll
        for (int off = 1; off < 32; off <<= 1) {
            int y = __shfl_down_sync(0xFFFFFFFFu, xsum, off);
            if (lane + off < 32) xsum += y;
        }
        if (lane == 0) wtot[wid] = xsum;       // warp total
        __syncthreads();
        int addhi = 0;
        for (int ww = wid + 1; ww < 8; ww++) addhi += wtot[ww];
        int suffix = xsum + addhi;             // # candidate keys with bin >= t
        int above  = suffix - v;               // # candidate keys with bin >  t
        if (suffix >= k && above < k) {        // exactly one thread matches
            s_prefix = pref | ((unsigned)t << shift);
            s_k      = k - above;
        }
    }
    __syncthreads();

    unsigned T  = s_prefix;   // exact 84th-largest key
    int     neq = s_k;        // #elements == T that get selected (earliest idx)
    for (int s = t; s < S_; s += 256) {
        unsigned kk = key[s];
        bool sel;
        if (kk > T) sel = true;
        else if (kk == T) {
            int eq = 0;
            for (int u = 0; u < s; u++) eq += (key[u] == T);
            sel = eq < neq;
        } else sel = false;
        float v = sc[s];
        g_amap[bc*S_ + s]    = sel ? v : 0.7f * v;
        g_selflag[bc*S_ + s] = sel ? 1 : 0;
    }
}

// ---------------- Kernel B: per-batch analytics (blocks 0..7) + copy ---------
__global__ void __launch_bounds__(256) kB(const float* __restrict__ w1,
                                          const float4* __restrict__ in4,
                                          float4* __restrict__ out4) {
    if (blockIdx.x >= 8) { copyChunk(in4, out4, CH_A + (blockIdx.x - 8u)); return; }
    int b = blockIdx.x;
    int t = threadIdx.x;
    unsigned lane = t & 31;
    int wid = t >> 5;
    const int NT = 256;
    __shared__ float  pw[S_];
    __shared__ float  binm[S_];
    __shared__ float  cnt[S_];
    __shared__ float  wsum[8];
    __shared__ unsigned long long wkey[8];
    __shared__ float4 wq[8];
    __shared__ float  s_mean, s_panchor;
    __shared__ float4 s_q;
    __shared__ int    s_anchor;

    // --- m[s] = sum_c amap; pw = m/12; total for mean ---
    float part = 0.f;
    for (int s = t; s < S_; s += NT) {
        float sm = 0.f;
        #pragma unroll
        for (int c = 0; c < C_; c++) sm += g_amap[(b*C_ + c)*S_ + s];
        binm[s] = sm;
        pw[s]   = sm * (1.f/12.f);
        part += sm;
    }
    #pragma unroll
    for (int off = 16; off > 0; off >>= 1) part += __shfl_down_sync(0xFFFFFFFFu, part, off);
    if (lane == 0) wsum[wid] = part;
    __syncthreads();                                              // (1)
    if (t < 8) {
        float v = wsum[t];
        #pragma unroll
        for (int off = 4; off > 0; off >>= 1) v += __shfl_down_sync(0xFFu, v, off);
        if (t == 0) s_mean = v / (float)S_;
    }
    __syncthreads();                                              // (2)
    float mean = s_mean;
    for (int s = t; s < S_; s += NT) binm[s] = (binm[s] > mean) ? 1.f : 0.f;
    // (binm[s] read/written by same thread — no barrier needed)

    // --- anchor = argmax_s binm[s]*pw[s], first index wins (u64 key) ---
    unsigned long long akey = 0ull;
    for (int s = t; s < S_; s += NT) {
        float v = binm[s] * pw[s];
        unsigned uv = __float_as_uint(v);
        if (uv == 0x80000000u) uv = 0u;        // canonicalize -0.0 -> +0.0 (integer, not elidable)
        unsigned fv = (uv & 0x80000000u) ? ~uv : (uv | 0x80000000u);
        unsigned long long k = ((unsigned long long)fv << 32) | (unsigned long long)(0xFFFFFFFFu - (unsigned)s);
        if (k > akey) akey = k;
    }
    #pragma unroll
    for (int off = 16; off > 0; off >>= 1) {
        unsigned long long o = __shfl_down_sync(0xFFFFFFFFu, akey, off);
        if (o > akey) akey = o;
    }
    if (lane == 0) wkey[wid] = akey;
    __syncthreads();                                              // (3)
    if (t < 8) {
        unsigned long long k = wkey[t];
        #pragma unroll
        for (int off = 4; off > 0; off >>= 1) {
            unsigned long long o = __shfl_down_sync(0xFFu, k, off);
            if (o > k) k = o;
        }
        if (t == 0) {
            int a = (int)(0xFFFFFFFFu - (unsigned)(k & 0xFFFFFFFFull));
            s_anchor = a;
            s_panchor = pw[a];
        }
    }
    __syncthreads();                                              // (4)
    int anchor = s_anchor;
    float ai = (float)(anchor / HH), aj = (float)(anchor % HH);

    // --- fused: q0 = pw.dist, q1 = pw.ang, A+/A- = sum pw^2 by sign ---
    float4 acc4 = make_float4(0.f, 0.f, 0.f, 0.f);
    for (int s = t; s < S_; s += NT) {
        float rx = ((float)(s / HH) - ai) / 28.0f;
        float ry = ((float)(s % HH) - aj) / 28.0f;
        float dist = sqrtf(rx*rx + ry*ry);
        float ang  = (atan2f(ry, rx) / (float)M_PI + 1.f) * 0.5f;
        float p = pw[s];
        acc4.x += p * dist;
        acc4.y += p * ang;
        if (p > 0.f) acc4.z += p*p; else if (p < 0.f) acc4.w += p*p;
    }
    #pragma unroll
    for (int off = 16; off > 0; off >>= 1) {
        acc4.x += __shfl_down_sync(0xFFFFFFFFu, acc4.x, off);
        acc4.y += __shfl_down_sync(0xFFFFFFFFu, acc4.y, off);
        acc4.z += __shfl_down_sync(0xFFFFFFFFu, acc4.z, off);
        acc4.w += __shfl_down_sync(0xFFFFFFFFu, acc4.w, off);
    }
    if (lane == 0) wq[wid] = acc4;
    __syncthreads();                                              // (5)
    if (t < 8) {
        float4 a = wq[t];
        #pragma unroll
        for (int off = 4; off > 0; off >>= 1) {
            a.x += __shfl_down_sync(0xFFu, a.x, off);
            a.y += __shfl_down_sync(0xFFu, a.y, off);
            a.z += __shfl_down_sync(0xFFu, a.z, off);
            a.w += __shfl_down_sync(0xFFu, a.w, off);
        }
        if (t == 0) s_q = a;
    }
    __syncthreads();                                              // (6)
    float Q0 = s_q.x, Q1 = s_q.y, AP = s_q.z, AM = s_q.w;
    float pa = s_panchor;

    // --- g_wk[k] = pa * v1[k] * (v1>0 ? A+ : A-),  v1 = q @ W1 ---
    for (int k = t; k < GCNH; k += NT) {
        float v = Q0 * w1[k] + Q1 * w1[GCNH + k];
        float wv = (v > 0.f) ? v * AP : ((v < 0.f) ? v * AM : 0.f);
        g_wk[b*GCNH + k] = pa * wv;
    }

    // --- count -> 3x3 conv -> composite int key (desc value, stable asc idx) ---
    for (int s = t; s < S_; s += NT) {
        int c = 0;
        #pragma unroll
        for (int ch = 0; ch < C_; ch++) c += g_selflag[(b*C_ + ch)*S_ + s];
        cnt[s] = (float)c;
    }
    __syncthreads();                                              // (7)
    for (int s = t; s < S_; s += NT) {
        int li = s / HH, lj = s % HH;
        float acc = 0.f;
        #pragma unroll
        for (int di = -1; di <= 1; di++) {
            #pragma unroll
            for (int dj = -1; dj <= 1; dj++) {
                int ni = li + di, nj = lj + dj;
                if (ni >= 0 && ni < HH && nj >= 0 && nj < HH) {
                    float kw = ((di == 0) ? 2.f : 1.f) * ((dj == 0) ? 2.f : 1.f);
                    acc += kw * cnt[ni*HH + nj];
                }
            }
        }
        g_key[b*S_ + s] = (int)acc * 1024 + (1023 - s);   // conv is exact small int
    }
}

// ---- kFuse: matvec (0..191) + rank (192..223) + copy (224..517) -------------
__global__ void __launch_bounds__(256) kFuse(const float* __restrict__ w2, int sn,
                                             const float4* __restrict__ in4,
                                             float4* __restrict__ out4) {
    int blk = blockIdx.x;
    int t   = threadIdx.x;
    if (blk >= 224) { copyChunk(in4, out4, CH_A + CH_B + (unsigned)(blk - 224)); return; }
    if (blk < B_ * 24) {
        // matvec: 32 output columns per block, 8-way j-split
        int b    = blk / 24;
        int tile = blk - b * 24;
        __shared__ float wk[GCNH];
        __shared__ float partr[256];
        for (int k = t; k < GCNH; k += 256) wk[k] = g_wk[b*GCNH + k];
        __syncthreads();
        int col = tile * 32 + (t & 31);
        int jq  = t >> 5;                      // 0..7
        const float* w2p = w2 + col;
        float acc = 0.f;
        int j0 = jq * 64;
        #pragma unroll 8
        for (int j = 0; j < 64; j++) acc += wk[j0 + j] * w2p[(size_t)(j0 + j) * D_];
        partr[t] = acc;
        __syncthreads();
        if (t < 32) {
            float o = 0.f;
            #pragma unroll
            for (int q = 0; q < 8; q++) o += partr[t + q*32];
            int c = tile * 32 + t;
            g_struct[b*D_ + c] = (o > 0.f) ? o : 0.2f * o;
        }
    } else {
        // stable descending rank via int keys
        int idx  = blk - B_ * 24;              // 0..31
        int b    = idx >> 2;
        int part = idx & 3;
        __shared__ int kk[S_];
        for (int s = t; s < S_; s += 256) kk[s] = g_key[b*S_ + s];
        __syncthreads();
        if (t < 196) {
            int s = part * 196 + t;
            int ks = kk[s];
            int r = 0;
            #pragma unroll 8
            for (int u = 0; u < S_; u++) r += (kk[u] > ks);
            if (r < sn) g_pidx[b*S_ + r] = s + 1;
        }
    }
}

// ---------------- Kernel tail: row-0 add + gather (tiny) ---------------------
__global__ void __launch_bounds__(256) kTail(const float4* __restrict__ in4,
                                             float4* __restrict__ out4,
                                             unsigned sn, unsigned ntail) {
    unsigned i = blockIdx.x * 256u + threadIdx.x;
    if (i >= ntail) return;
    if (i < 1536u) {                            // 8 batches * 192: row 0 with struct add
        unsigned b  = i / ROWF4;
        unsigned k4 = i - b * ROWF4;
        float4 v = in4[b*BATF4 + k4];
        float4 st = ((const float4*)g_struct)[b*ROWF4 + k4];
        v.x += st.x; v.y += st.y; v.z += st.z; v.w += st.w;
        out4[b*BATF4 + k4] = v;
    } else {                                    // gather selected rows
        unsigned j  = i - 1536u;
        unsigned rr = j / ROWF4;                // b*sn + jj
        unsigned k4 = j - rr * ROWF4;
        unsigned b  = rr / sn;
        unsigned jj = rr - b * sn;
        unsigned row = (unsigned)g_pidx[b*S_ + jj];
        out4[NHS4 + j] = in4[(b*785u + row)*ROWF4 + k4];
    }
}

// ---------------- launch ----------------
extern "C" void kernel_launch(void* const* d_in, const int* in_sizes, int n_in,
                              void* d_out, int out_size) {
    const float* hs = (const float*)d_in[0];
    const float* x  = (const float*)d_in[1];
    const float* w1 = (const float*)d_in[2];
    const float* w2 = (const float*)d_in[3];
    (void)in_sizes; (void)n_in;

    int sn = out_size / (B_ * D_) - NTOK;     // selected rows per batch
    if (sn < 1) sn = 1;
    if (sn > S_) sn = S_;

    const float4* in4 = (const float4*)hs;
    float4* out4 = (float4*)d_out;

    kA<<<96 + CH_A, 256>>>(x, in4, out4);
    kB<<<8 + CH_B, 256>>>(w1, in4, out4);
    kFuse<<<224 + CH_F, 256>>>(w2, sn, in4, out4);

    unsigned ntail = 1536u + (unsigned)(B_ * sn) * ROWF4;
    kTail<<<(ntail + 255u) / 256u, 256>>>(in4, out4, (unsigned)sn, ntail);
}